// round 10
// baseline (speedup 1.0000x reference)
#include <cuda_runtime.h>

#define D 128
#define TILE_M 64
#define KB 32
#define MAXN 50176
#define MAXE 524288
#define SCAN_B 1024

typedef unsigned long long u64;

// packed 2xfp32 FMA: acc = a*b + acc  (FFMA2, sm_103a)
#define FMA2(acc, a, b) \
    asm("fma.rn.f32x2 %0, %1, %2, %0;" : "+l"(acc) : "l"(a), "l"(b))
#define DUP_F32(d, s) \
    asm("mov.b64 %0, {%1, %1};" : "=l"(d) : "f"(s))
#define UNPACK2(lo, hi, p) \
    asm("mov.b64 {%0, %1}, %2;" : "=f"(lo), "=f"(hi) : "l"(p))

// ---- device scratch (no allocations allowed) ----
__device__ float g_agg[MAXN * D];    // x + sum(relu(x_src+ea)) per node
__device__ float g_h[MAXN * D];
__device__ float g_x1[MAXN * D];
__device__ float g_ea_csr[MAXE * D]; // edge_attr permuted into CSR order (256 MB)
__device__ float g_sum[D];
__device__ float g_sq[D];
__device__ float g_scale[D];
__device__ float g_shift[D];
// CSR build scratch
__device__ int g_cnt[MAXN];       // zero at module load; re-zeroed by scatter each launch
__device__ int g_rowptr[MAXN];
__device__ int g_fill[MAXN];      // after scatter: row end
__device__ int g_se[MAXE];        // CSR-ordered src node id
__device__ int g_epos[MAXE];      // original edge id -> CSR position
__device__ int g_bsum[64];

// ================= CSR build (once per launch) =================
__global__ void hist_kernel(const int* __restrict__ ei, int* __restrict__ cnt, int E) {
    int i = blockIdx.x * blockDim.x + threadIdx.x;
    if (i < E) atomicAdd(&cnt[__ldg(ei + E + i)], 1);
}

__global__ __launch_bounds__(SCAN_B) void scan1_kernel(
    const int* __restrict__ cnt, int* __restrict__ rowptr,
    int* __restrict__ bsum, int n)
{
    __shared__ int sh[SCAN_B];
    int t = threadIdx.x;
    int i = blockIdx.x * SCAN_B + t;
    int v = (i < n) ? cnt[i] : 0;
    sh[t] = v;
    __syncthreads();
#pragma unroll
    for (int off = 1; off < SCAN_B; off <<= 1) {
        int add = (t >= off) ? sh[t - off] : 0;
        __syncthreads();
        sh[t] += add;
        __syncthreads();
    }
    if (i < n) rowptr[i] = sh[t] - v;
    if (t == SCAN_B - 1) bsum[blockIdx.x] = sh[t];
}

// scan2 merged in: each block sums bsum[0..blockIdx.x) itself (<= 49 ints)
__global__ __launch_bounds__(SCAN_B) void scan23_kernel(
    int* __restrict__ rowptr, int* __restrict__ fill,
    const int* __restrict__ bsum, int n)
{
    __shared__ int boff_s;
    if (threadIdx.x == 0) {
        int acc = 0;
        for (int b = 0; b < blockIdx.x; b++) acc += bsum[b];
        boff_s = acc;
    }
    __syncthreads();
    int i = blockIdx.x * SCAN_B + threadIdx.x;
    if (i < n) {
        int r = rowptr[i] + boff_s;
        rowptr[i] = r;
        fill[i] = r;
    }
}

// scatter: write src id + edge->CSR-position maps; re-zero cnt for next replay
__global__ void scatter_kernel(const int* __restrict__ ei, int* __restrict__ fill,
                               int* __restrict__ se, int* __restrict__ epos,
                               int* __restrict__ cnt, int E, int N) {
    int e = blockIdx.x * blockDim.x + threadIdx.x;
    if (e < N) cnt[e] = 0;
    if (e < E) {
        int s = __ldg(ei + e);
        int d = __ldg(ei + E + e);
        int idx = atomicAdd(&fill[d], 1);
        se[idx] = s;
        epos[e] = idx;
    }
}

// permute ea into CSR order: sequential read, scatter write (fire-and-forget)
__global__ __launch_bounds__(256) void permute_ea_kernel(
    const float* __restrict__ ea, const int* __restrict__ epos,
    float* __restrict__ ea_csr, int E)
{
    int e = blockIdx.x * 8 + (threadIdx.x >> 5);
    if (e >= E) return;
    int lane = threadIdx.x & 31;
    float4 v = __ldg((const float4*)ea + (size_t)e * 32 + lane);
    int idx = __ldg(epos + e);
    ((float4*)ea_csr)[(size_t)idx * 32 + lane] = v;
}

// ========== per-layer aggregate: warp per node; ea now sequential ==========
// agg[v] = x[v] + sum_{e: dst=v} relu(x[src_e] + ea_csr[j]); also zeroes BN stats
__global__ __launch_bounds__(256) void agg_kernel(
    const float* __restrict__ x,
    const float* __restrict__ ea_csr,
    const int* __restrict__ rowptr, const int* __restrict__ rowend,
    const int* __restrict__ se,
    float* __restrict__ agg, float* __restrict__ ssum, float* __restrict__ ssq, int N)
{
    if (blockIdx.x == 0 && threadIdx.x < D) {
        ssum[threadIdx.x] = 0.f;
        ssq[threadIdx.x] = 0.f;
    }
    int v = blockIdx.x * 8 + (threadIdx.x >> 5);
    if (v >= N) return;
    int lane = threadIdx.x & 31;
    int j   = __ldg(rowptr + v);
    int end = __ldg(rowend + v);
    const float4* x4  = (const float4*)x;
    const float4* ea4 = (const float4*)ea_csr;
    float4 acc = __ldg(x4 + (size_t)v * 32 + lane);
    for (; j < end; j++) {
        int s = __ldg(se + j);                        // sequential, L1-resident
        float4 xv = __ldg(x4 + (size_t)s * 32 + lane);   // random, L2-resident
        float4 ev = __ldg(ea4 + (size_t)j * 32 + lane);  // SEQUENTIAL DRAM stream
        acc.x += fmaxf(xv.x + ev.x, 0.f);
        acc.y += fmaxf(xv.y + ev.y, 0.f);
        acc.z += fmaxf(xv.z + ev.z, 0.f);
        acc.w += fmaxf(xv.w + ev.w, 0.f);
    }
    ((float4*)agg)[(size_t)v * 32 + lane] = acc;
}

// ---- fused GEMM (FFMA2 inner loop):
//  MODE 0 = A@W1+b1, write h, accumulate BN stats   (A = x+agg precombined)
//  MODE 1 = relu(A*scale+shift)@W2+b2, relu, write out ----
template<int MODE>
__global__ __launch_bounds__(128)
void gemm_kernel(const float* __restrict__ A,
                 const float* __restrict__ W, const float* __restrict__ bias,
                 const float* __restrict__ scale, const float* __restrict__ shift,
                 float* __restrict__ out,
                 float* __restrict__ ssum, float* __restrict__ ssq, int M)
{
    __shared__ float W_s[KB][D];
    __shared__ float t_s[KB][TILE_M + 4];
    __shared__ float bn_s[2][D];
    __shared__ float st_s[2][D];

    int t = threadIdx.x;
    int cg = t >> 3;
    int rg = t & 7;
    int row_base = blockIdx.x * TILE_M;

    if (MODE == 1) {
        bn_s[0][t] = __ldg(scale + t);
        bn_s[1][t] = __ldg(shift + t);
        __syncthreads();
    }

    u64 accp[8][4];
#pragma unroll
    for (int r = 0; r < 8; r++)
#pragma unroll
        for (int c = 0; c < 4; c++) accp[r][c] = 0ULL;

    for (int kb = 0; kb < D; kb += KB) {
#pragma unroll
        for (int i = 0; i < 8; i++) {
            int f4 = i * 128 + t;
            int k  = f4 >> 5;
            int c4 = f4 & 31;
            float4 w = __ldg((const float4*)(W + (size_t)(kb + k) * D) + c4);
            *((float4*)&W_s[k][c4 * 4]) = w;
        }
#pragma unroll
        for (int i = 0; i < 4; i++) {
            int f4 = i * 128 + t;
            int r  = f4 >> 3;
            int k4 = f4 & 7;
            int grow = row_base + r;
            float4 v = make_float4(0.f, 0.f, 0.f, 0.f);
            if (grow < M) {
                float4 a = __ldg((const float4*)(A + (size_t)grow * D + kb) + k4);
                if (MODE == 0) {
                    v = a;
                } else {
                    int k0 = kb + k4 * 4;
                    v.x = fmaxf(fmaf(a.x, bn_s[0][k0 + 0], bn_s[1][k0 + 0]), 0.f);
                    v.y = fmaxf(fmaf(a.y, bn_s[0][k0 + 1], bn_s[1][k0 + 1]), 0.f);
                    v.z = fmaxf(fmaf(a.z, bn_s[0][k0 + 2], bn_s[1][k0 + 2]), 0.f);
                    v.w = fmaxf(fmaf(a.w, bn_s[0][k0 + 3], bn_s[1][k0 + 3]), 0.f);
                }
            }
            int kk = k4 * 4;
            t_s[kk + 0][r] = v.x;
            t_s[kk + 1][r] = v.y;
            t_s[kk + 2][r] = v.z;
            t_s[kk + 3][r] = v.w;
        }
        __syncthreads();

#pragma unroll 8
        for (int k = 0; k < KB; k++) {
            float a[8];
            const float4* ap = (const float4*)&t_s[k][rg * 8];
            *(float4*)&a[0] = ap[0];
            *(float4*)&a[4] = ap[1];
            ulonglong2 w01 = *(const ulonglong2*)&W_s[k][cg * 8];
            ulonglong2 w23 = *(const ulonglong2*)&W_s[k][cg * 8 + 4];
            u64 wp0 = w01.x, wp1 = w01.y, wp2 = w23.x, wp3 = w23.y;
#pragma unroll
            for (int r = 0; r < 8; r++) {
                u64 ad;
                DUP_F32(ad, a[r]);
                FMA2(accp[r][0], ad, wp0);
                FMA2(accp[r][1], ad, wp1);
                FMA2(accp[r][2], ad, wp2);
                FMA2(accp[r][3], ad, wp3);
            }
        }
        __syncthreads();
    }

    float bv[8];
#pragma unroll
    for (int c = 0; c < 8; c++) bv[c] = __ldg(bias + cg * 8 + c);

    if (MODE == 0) {
        st_s[0][t] = 0.f;
        st_s[1][t] = 0.f;
        __syncthreads();
        float csum[8], csq[8];
#pragma unroll
        for (int c = 0; c < 8; c++) { csum[c] = 0.f; csq[c] = 0.f; }
#pragma unroll
        for (int r = 0; r < 8; r++) {
            int row = row_base + rg * 8 + r;
            if (row < M) {
                float o[8];
#pragma unroll
                for (int cp = 0; cp < 4; cp++)
                    UNPACK2(o[2 * cp], o[2 * cp + 1], accp[r][cp]);
#pragma unroll
                for (int c = 0; c < 8; c++) {
                    o[c] += bv[c];
                    csum[c] += o[c];
                    csq[c]  += o[c] * o[c];
                }
                float4* op = (float4*)(out + (size_t)row * D + cg * 8);
                op[0] = make_float4(o[0], o[1], o[2], o[3]);
                op[1] = make_float4(o[4], o[5], o[6], o[7]);
            }
        }
#pragma unroll
        for (int c = 0; c < 8; c++) {
            atomicAdd(&st_s[0][cg * 8 + c], csum[c]);
            atomicAdd(&st_s[1][cg * 8 + c], csq[c]);
        }
        __syncthreads();
        atomicAdd(&ssum[t], st_s[0][t]);
        atomicAdd(&ssq[t],  st_s[1][t]);
    } else {
#pragma unroll
        for (int r = 0; r < 8; r++) {
            int row = row_base + rg * 8 + r;
            if (row < M) {
                float o[8];
#pragma unroll
                for (int cp = 0; cp < 4; cp++)
                    UNPACK2(o[2 * cp], o[2 * cp + 1], accp[r][cp]);
#pragma unroll
                for (int c = 0; c < 8; c++) o[c] = fmaxf(o[c] + bv[c], 0.f);
                float4* op = (float4*)(out + (size_t)row * D + cg * 8);
                op[0] = make_float4(o[0], o[1], o[2], o[3]);
                op[1] = make_float4(o[4], o[5], o[6], o[7]);
            }
        }
    }
}

// ---- fold BN stats + gamma/beta into per-feature scale/shift ----
__global__ void finalize_kernel(const float* __restrict__ ssum, const float* __restrict__ ssq,
                                const float* __restrict__ gamma, const float* __restrict__ beta,
                                float* __restrict__ scale, float* __restrict__ shift, float invN)
{
    int i = threadIdx.x;
    float m  = ssum[i] * invN;
    float v  = fmaf(ssq[i], invN, -m * m);
    float r  = rsqrtf(v + 1e-5f);
    float sc = r * __ldg(gamma + i);
    scale[i] = sc;
    shift[i] = fmaf(-m, sc, __ldg(beta + i));
}

extern "C" void kernel_launch(void* const* d_in, const int* in_sizes, int n_in,
                              void* d_out, int out_size) {
    const float* x     = (const float*)d_in[0];
    const int*   ei    = (const int*)d_in[1];       // int32 (JAX demotes int64)
    const float* ea    = (const float*)d_in[2];
    const float* W1    = (const float*)d_in[3];
    const float* b1    = (const float*)d_in[4];
    const float* gamma = (const float*)d_in[5];
    const float* beta  = (const float*)d_in[6];
    const float* W2    = (const float*)d_in[7];
    const float* b2    = (const float*)d_in[8];

    int M = in_sizes[0] / D;      // nodes
    int E = in_sizes[2] / D;      // edges
    int L = in_sizes[3] / (D * D);

    float *p_agg, *p_h, *p_x1, *p_eacsr, *p_sum, *p_sq, *p_scale, *p_shift;
    int *p_cnt, *p_rowptr, *p_fill, *p_se, *p_epos, *p_bsum;
    cudaGetSymbolAddress((void**)&p_agg,   g_agg);
    cudaGetSymbolAddress((void**)&p_h,     g_h);
    cudaGetSymbolAddress((void**)&p_x1,    g_x1);
    cudaGetSymbolAddress((void**)&p_eacsr, g_ea_csr);
    cudaGetSymbolAddress((void**)&p_sum,   g_sum);
    cudaGetSymbolAddress((void**)&p_sq,    g_sq);
    cudaGetSymbolAddress((void**)&p_scale, g_scale);
    cudaGetSymbolAddress((void**)&p_shift, g_shift);
    cudaGetSymbolAddress((void**)&p_cnt,    g_cnt);
    cudaGetSymbolAddress((void**)&p_rowptr, g_rowptr);
    cudaGetSymbolAddress((void**)&p_fill,   g_fill);
    cudaGetSymbolAddress((void**)&p_se,     g_se);
    cudaGetSymbolAddress((void**)&p_epos,   g_epos);
    cudaGetSymbolAddress((void**)&p_bsum,   g_bsum);

    int gemm_blocks = (M + TILE_M - 1) / TILE_M;
    int eb = (E + 255) / 256;
    int nbscan = (M + SCAN_B - 1) / SCAN_B;
    int agg_blocks = (M + 7) / 8;
    int perm_blocks = (E + 7) / 8;

    // ---- build CSR + permute ea once (edge structure constant across layers)
    hist_kernel<<<eb, 256>>>(ei, p_cnt, E);
    scan1_kernel<<<nbscan, SCAN_B>>>(p_cnt, p_rowptr, p_bsum, M);
    scan23_kernel<<<nbscan, SCAN_B>>>(p_rowptr, p_fill, p_bsum, M);
    scatter_kernel<<<eb, 256>>>(ei, p_fill, p_se, p_epos, p_cnt, E, M);
    permute_ea_kernel<<<perm_blocks, 256>>>(ea, p_epos, p_eacsr, E);
    // after scatter: p_fill[v] == row end of v

    for (int l = 0; l < L; l++) {
        const float* xin = (l == 0) ? x : p_x1;
        float* xout = (l == L - 1) ? (float*)d_out : p_x1;

        agg_kernel<<<agg_blocks, 256>>>(xin, p_eacsr, p_rowptr, p_fill, p_se,
                                        p_agg, p_sum, p_sq, M);
        gemm_kernel<0><<<gemm_blocks, 128>>>(p_agg,
                                             W1 + (size_t)l * D * D, b1 + (size_t)l * D,
                                             nullptr, nullptr, p_h, p_sum, p_sq, M);
        finalize_kernel<<<1, D>>>(p_sum, p_sq, gamma + (size_t)l * D, beta + (size_t)l * D,
                                  p_scale, p_shift, 1.0f / (float)M);
        gemm_kernel<1><<<gemm_blocks, 128>>>(p_h,
                                             W2 + (size_t)l * D * D, b2 + (size_t)l * D,
                                             p_scale, p_shift, xout, nullptr, nullptr, M);
    }
}

// round 11
// speedup vs baseline: 1.2541x; 1.2541x over previous
#include <cuda_runtime.h>

#define D 128
#define TILE_M 64
#define KB 32
#define MAXN 50176
#define MAXE 524288
#define SCAN_B 1024
#define PIPE 4

typedef unsigned long long u64;

// packed 2xfp32 FMA: acc = a*b + acc  (FFMA2, sm_103a)
#define FMA2(acc, a, b) \
    asm("fma.rn.f32x2 %0, %1, %2, %0;" : "+l"(acc) : "l"(a), "l"(b))
#define DUP_F32(d, s) \
    asm("mov.b64 %0, {%1, %1};" : "=l"(d) : "f"(s))
#define UNPACK2(lo, hi, p) \
    asm("mov.b64 {%0, %1}, %2;" : "=f"(lo), "=f"(hi) : "l"(p))

__device__ __forceinline__ void cpa16(unsigned int dst, const void* src) {
    asm volatile("cp.async.cg.shared.global [%0], [%1], 16;" :: "r"(dst), "l"(src));
}
// streaming copy: L2 evict-first so the single-use ea stream doesn't evict x
__device__ __forceinline__ void cpa16_stream(unsigned int dst, const void* src, u64 pol) {
    asm volatile("cp.async.cg.shared.global.L2::cache_hint [%0], [%1], 16, %2;"
                 :: "r"(dst), "l"(src), "l"(pol));
}
#define CP_COMMIT() asm volatile("cp.async.commit_group;" ::: "memory")
#define CP_WAIT(n)  asm volatile("cp.async.wait_group %0;" :: "n"(n) : "memory")

// ---- device scratch (no allocations allowed) ----
__device__ float g_agg[MAXN * D];   // x + sum(relu(x_src+ea)) per node
__device__ float g_h[MAXN * D];
__device__ float g_x1[MAXN * D];
__device__ float g_sum[D];
__device__ float g_sq[D];
__device__ float g_scale[D];
__device__ float g_shift[D];
// CSR build scratch
__device__ int g_cnt[MAXN];       // zero at module load; re-zeroed by scatter each launch
__device__ int g_rowptr[MAXN];
__device__ int g_fill[MAXN];      // after scatter: row end
__device__ int g_perm[MAXE];      // CSR-ordered original edge id (for ea)
__device__ int g_se[MAXE];        // CSR-ordered src node id
__device__ int g_bsum[64];

// ================= CSR build (once per launch, 4 kernels) =================
__global__ void hist_kernel(const int* __restrict__ ei, int* __restrict__ cnt, int E) {
    int i = blockIdx.x * blockDim.x + threadIdx.x;
    if (i < E) atomicAdd(&cnt[__ldg(ei + E + i)], 1);
}

__global__ __launch_bounds__(SCAN_B) void scan1_kernel(
    const int* __restrict__ cnt, int* __restrict__ rowptr,
    int* __restrict__ bsum, int n)
{
    __shared__ int sh[SCAN_B];
    int t = threadIdx.x;
    int i = blockIdx.x * SCAN_B + t;
    int v = (i < n) ? cnt[i] : 0;
    sh[t] = v;
    __syncthreads();
#pragma unroll
    for (int off = 1; off < SCAN_B; off <<= 1) {
        int add = (t >= off) ? sh[t - off] : 0;
        __syncthreads();
        sh[t] += add;
        __syncthreads();
    }
    if (i < n) rowptr[i] = sh[t] - v;
    if (t == SCAN_B - 1) bsum[blockIdx.x] = sh[t];
}

// scan2 merged in: each block sums bsum[0..blockIdx.x) itself (<= 49 ints)
__global__ __launch_bounds__(SCAN_B) void scan23_kernel(
    int* __restrict__ rowptr, int* __restrict__ fill,
    const int* __restrict__ bsum, int n)
{
    __shared__ int boff_s;
    if (threadIdx.x == 0) {
        int acc = 0;
        for (int b = 0; b < blockIdx.x; b++) acc += bsum[b];
        boff_s = acc;
    }
    __syncthreads();
    int i = blockIdx.x * SCAN_B + threadIdx.x;
    if (i < n) {
        int r = rowptr[i] + boff_s;
        rowptr[i] = r;
        fill[i] = r;
    }
}

// scatter: write edge id + src id in CSR order; re-zero cnt for next replay
__global__ void scatter_kernel(const int* __restrict__ ei, int* __restrict__ fill,
                               int* __restrict__ perm, int* __restrict__ se,
                               int* __restrict__ cnt, int E, int N) {
    int e = blockIdx.x * blockDim.x + threadIdx.x;
    if (e < N) cnt[e] = 0;
    if (e < E) {
        int s = __ldg(ei + e);
        int d = __ldg(ei + E + e);
        int idx = atomicAdd(&fill[d], 1);
        perm[idx] = e;
        se[idx] = s;
    }
}

// ========== per-layer aggregate: warp per node, cp.async pipeline ==========
// ea copies use L2::evict_first so the 256MB single-use stream preserves
// the L2 residency of x (25.6MB), keeping the random x-gather off DRAM.
__global__ __launch_bounds__(256) void agg_kernel(
    const float* __restrict__ x,
    const float* __restrict__ ea,
    const int* __restrict__ rowptr, const int* __restrict__ rowend,
    const int* __restrict__ perm, const int* __restrict__ se,
    float* __restrict__ agg, float* __restrict__ ssum, float* __restrict__ ssq, int N)
{
    __shared__ float4 buf[8][PIPE][2][32];   // 32 KB: warp, slot, {x,ea}, lane

    if (blockIdx.x == 0 && threadIdx.x < D) {
        ssum[threadIdx.x] = 0.f;
        ssq[threadIdx.x] = 0.f;
    }
    int w = threadIdx.x >> 5;
    int lane = threadIdx.x & 31;
    int v = blockIdx.x * 8 + w;
    if (v >= N) return;

    u64 pol;
    asm("createpolicy.fractional.L2::evict_first.b64 %0, 1.0;" : "=l"(pol));

    int j   = __ldg(rowptr + v);
    int end = __ldg(rowend + v);
    int deg = end - j;

    const float4* x4  = (const float4*)x;
    const float4* ea4 = (const float4*)ea;
    float4 acc = __ldg(x4 + (size_t)v * 32 + lane);

    unsigned int bx = (unsigned int)__cvta_generic_to_shared(&buf[w][0][0][lane]);
    // slot p: x part at bx + p*1024, ea part at bx + p*1024 + 512

    // prologue: ALWAYS commit PIPE groups (empty if deg < PIPE)
#pragma unroll
    for (int p = 0; p < PIPE; p++) {
        if (p < deg) {
            int e = __ldg(perm + j + p);
            int s = __ldg(se + j + p);
            cpa16(bx + p * 1024, x4 + (size_t)s * 32 + lane);
            cpa16_stream(bx + p * 1024 + 512, ea4 + (size_t)e * 32 + lane, pol);
        }
        CP_COMMIT();
    }

    int slot = 0;
    for (int i = 0; i < deg; i++) {
        int nj = j + i + PIPE;
        bool isu = (nj < end);               // warp-uniform
        int e = 0, s = 0;
        if (isu) {
            e = __ldg(perm + nj);
            s = __ldg(se + nj);
        }
        CP_WAIT(PIPE - 1);                    // group i complete -> slot ready
        float4 xv = buf[w][slot][0][lane];
        float4 ev = buf[w][slot][1][lane];
        if (isu) {
            cpa16(bx + slot * 1024, x4 + (size_t)s * 32 + lane);
            cpa16_stream(bx + slot * 1024 + 512, ea4 + (size_t)e * 32 + lane, pol);
        }
        CP_COMMIT();
        acc.x += fmaxf(xv.x + ev.x, 0.f);
        acc.y += fmaxf(xv.y + ev.y, 0.f);
        acc.z += fmaxf(xv.z + ev.z, 0.f);
        acc.w += fmaxf(xv.w + ev.w, 0.f);
        slot = (slot + 1) & (PIPE - 1);
    }
    asm volatile("cp.async.wait_all;" ::: "memory");
    ((float4*)agg)[(size_t)v * 32 + lane] = acc;
}

// ---- fused GEMM (FFMA2 inner loop):
//  MODE 0 = A@W1+b1, write h, accumulate BN stats   (A = x+agg precombined)
//  MODE 1 = relu(A*scale+shift)@W2+b2, relu, write out ----
template<int MODE>
__global__ __launch_bounds__(128)
void gemm_kernel(const float* __restrict__ A,
                 const float* __restrict__ W, const float* __restrict__ bias,
                 const float* __restrict__ scale, const float* __restrict__ shift,
                 float* __restrict__ out,
                 float* __restrict__ ssum, float* __restrict__ ssq, int M)
{
    __shared__ float W_s[KB][D];
    __shared__ float t_s[KB][TILE_M + 4];
    __shared__ float bn_s[2][D];
    __shared__ float st_s[2][D];

    int t = threadIdx.x;
    int cg = t >> 3;
    int rg = t & 7;
    int row_base = blockIdx.x * TILE_M;

    if (MODE == 1) {
        bn_s[0][t] = __ldg(scale + t);
        bn_s[1][t] = __ldg(shift + t);
        __syncthreads();
    }

    u64 accp[8][4];
#pragma unroll
    for (int r = 0; r < 8; r++)
#pragma unroll
        for (int c = 0; c < 4; c++) accp[r][c] = 0ULL;

    for (int kb = 0; kb < D; kb += KB) {
#pragma unroll
        for (int i = 0; i < 8; i++) {
            int f4 = i * 128 + t;
            int k  = f4 >> 5;
            int c4 = f4 & 31;
            float4 w = __ldg((const float4*)(W + (size_t)(kb + k) * D) + c4);
            *((float4*)&W_s[k][c4 * 4]) = w;
        }
#pragma unroll
        for (int i = 0; i < 4; i++) {
            int f4 = i * 128 + t;
            int r  = f4 >> 3;
            int k4 = f4 & 7;
            int grow = row_base + r;
            float4 v = make_float4(0.f, 0.f, 0.f, 0.f);
            if (grow < M) {
                float4 a = __ldg((const float4*)(A + (size_t)grow * D + kb) + k4);
                if (MODE == 0) {
                    v = a;
                } else {
                    int k0 = kb + k4 * 4;
                    v.x = fmaxf(fmaf(a.x, bn_s[0][k0 + 0], bn_s[1][k0 + 0]), 0.f);
                    v.y = fmaxf(fmaf(a.y, bn_s[0][k0 + 1], bn_s[1][k0 + 1]), 0.f);
                    v.z = fmaxf(fmaf(a.z, bn_s[0][k0 + 2], bn_s[1][k0 + 2]), 0.f);
                    v.w = fmaxf(fmaf(a.w, bn_s[0][k0 + 3], bn_s[1][k0 + 3]), 0.f);
                }
            }
            int kk = k4 * 4;
            t_s[kk + 0][r] = v.x;
            t_s[kk + 1][r] = v.y;
            t_s[kk + 2][r] = v.z;
            t_s[kk + 3][r] = v.w;
        }
        __syncthreads();

#pragma unroll 8
        for (int k = 0; k < KB; k++) {
            float a[8];
            const float4* ap = (const float4*)&t_s[k][rg * 8];
            *(float4*)&a[0] = ap[0];
            *(float4*)&a[4] = ap[1];
            ulonglong2 w01 = *(const ulonglong2*)&W_s[k][cg * 8];
            ulonglong2 w23 = *(const ulonglong2*)&W_s[k][cg * 8 + 4];
            u64 wp0 = w01.x, wp1 = w01.y, wp2 = w23.x, wp3 = w23.y;
#pragma unroll
            for (int r = 0; r < 8; r++) {
                u64 ad;
                DUP_F32(ad, a[r]);
                FMA2(accp[r][0], ad, wp0);
                FMA2(accp[r][1], ad, wp1);
                FMA2(accp[r][2], ad, wp2);
                FMA2(accp[r][3], ad, wp3);
            }
        }
        __syncthreads();
    }

    float bv[8];
#pragma unroll
    for (int c = 0; c < 8; c++) bv[c] = __ldg(bias + cg * 8 + c);

    if (MODE == 0) {
        st_s[0][t] = 0.f;
        st_s[1][t] = 0.f;
        __syncthreads();
        float csum[8], csq[8];
#pragma unroll
        for (int c = 0; c < 8; c++) { csum[c] = 0.f; csq[c] = 0.f; }
#pragma unroll
        for (int r = 0; r < 8; r++) {
            int row = row_base + rg * 8 + r;
            if (row < M) {
                float o[8];
#pragma unroll
                for (int cp = 0; cp < 4; cp++)
                    UNPACK2(o[2 * cp], o[2 * cp + 1], accp[r][cp]);
#pragma unroll
                for (int c = 0; c < 8; c++) {
                    o[c] += bv[c];
                    csum[c] += o[c];
                    csq[c]  += o[c] * o[c];
                }
                float4* op = (float4*)(out + (size_t)row * D + cg * 8);
                op[0] = make_float4(o[0], o[1], o[2], o[3]);
                op[1] = make_float4(o[4], o[5], o[6], o[7]);
            }
        }
#pragma unroll
        for (int c = 0; c < 8; c++) {
            atomicAdd(&st_s[0][cg * 8 + c], csum[c]);
            atomicAdd(&st_s[1][cg * 8 + c], csq[c]);
        }
        __syncthreads();
        atomicAdd(&ssum[t], st_s[0][t]);
        atomicAdd(&ssq[t],  st_s[1][t]);
    } else {
#pragma unroll
        for (int r = 0; r < 8; r++) {
            int row = row_base + rg * 8 + r;
            if (row < M) {
                float o[8];
#pragma unroll
                for (int cp = 0; cp < 4; cp++)
                    UNPACK2(o[2 * cp], o[2 * cp + 1], accp[r][cp]);
#pragma unroll
                for (int c = 0; c < 8; c++) o[c] = fmaxf(o[c] + bv[c], 0.f);
                float4* op = (float4*)(out + (size_t)row * D + cg * 8);
                op[0] = make_float4(o[0], o[1], o[2], o[3]);
                op[1] = make_float4(o[4], o[5], o[6], o[7]);
            }
        }
    }
}

// ---- fold BN stats + gamma/beta into per-feature scale/shift ----
__global__ void finalize_kernel(const float* __restrict__ ssum, const float* __restrict__ ssq,
                                const float* __restrict__ gamma, const float* __restrict__ beta,
                                float* __restrict__ scale, float* __restrict__ shift, float invN)
{
    int i = threadIdx.x;
    float m  = ssum[i] * invN;
    float v  = fmaf(ssq[i], invN, -m * m);
    float r  = rsqrtf(v + 1e-5f);
    float sc = r * __ldg(gamma + i);
    scale[i] = sc;
    shift[i] = fmaf(-m, sc, __ldg(beta + i));
}

extern "C" void kernel_launch(void* const* d_in, const int* in_sizes, int n_in,
                              void* d_out, int out_size) {
    const float* x     = (const float*)d_in[0];
    const int*   ei    = (const int*)d_in[1];       // int32 (JAX demotes int64)
    const float* ea    = (const float*)d_in[2];
    const float* W1    = (const float*)d_in[3];
    const float* b1    = (const float*)d_in[4];
    const float* gamma = (const float*)d_in[5];
    const float* beta  = (const float*)d_in[6];
    const float* W2    = (const float*)d_in[7];
    const float* b2    = (const float*)d_in[8];

    int M = in_sizes[0] / D;      // nodes
    int E = in_sizes[2] / D;      // edges
    int L = in_sizes[3] / (D * D);

    float *p_agg, *p_h, *p_x1, *p_sum, *p_sq, *p_scale, *p_shift;
    int *p_cnt, *p_rowptr, *p_fill, *p_perm, *p_se, *p_bsum;
    cudaGetSymbolAddress((void**)&p_agg,   g_agg);
    cudaGetSymbolAddress((void**)&p_h,     g_h);
    cudaGetSymbolAddress((void**)&p_x1,    g_x1);
    cudaGetSymbolAddress((void**)&p_sum,   g_sum);
    cudaGetSymbolAddress((void**)&p_sq,    g_sq);
    cudaGetSymbolAddress((void**)&p_scale, g_scale);
    cudaGetSymbolAddress((void**)&p_shift, g_shift);
    cudaGetSymbolAddress((void**)&p_cnt,    g_cnt);
    cudaGetSymbolAddress((void**)&p_rowptr, g_rowptr);
    cudaGetSymbolAddress((void**)&p_fill,   g_fill);
    cudaGetSymbolAddress((void**)&p_perm,   g_perm);
    cudaGetSymbolAddress((void**)&p_se,     g_se);
    cudaGetSymbolAddress((void**)&p_bsum,   g_bsum);

    int gemm_blocks = (M + TILE_M - 1) / TILE_M;
    int eb = (E + 255) / 256;
    int nbscan = (M + SCAN_B - 1) / SCAN_B;
    int agg_blocks = (M + 7) / 8;

    // ---- build CSR once (4 launches; scatter re-zeroes cnt for next replay)
    hist_kernel<<<eb, 256>>>(ei, p_cnt, E);
    scan1_kernel<<<nbscan, SCAN_B>>>(p_cnt, p_rowptr, p_bsum, M);
    scan23_kernel<<<nbscan, SCAN_B>>>(p_rowptr, p_fill, p_bsum, M);
    scatter_kernel<<<eb, 256>>>(ei, p_fill, p_perm, p_se, p_cnt, E, M);
    // after scatter: p_fill[v] == row end of v

    for (int l = 0; l < L; l++) {
        const float* xin = (l == 0) ? x : p_x1;
        float* xout = (l == L - 1) ? (float*)d_out : p_x1;

        agg_kernel<<<agg_blocks, 256>>>(xin, ea, p_rowptr, p_fill, p_perm, p_se,
                                        p_agg, p_sum, p_sq, M);
        gemm_kernel<0><<<gemm_blocks, 128>>>(p_agg,
                                             W1 + (size_t)l * D * D, b1 + (size_t)l * D,
                                             nullptr, nullptr, p_h, p_sum, p_sq, M);
        finalize_kernel<<<1, D>>>(p_sum, p_sq, gamma + (size_t)l * D, beta + (size_t)l * D,
                                  p_scale, p_shift, 1.0f / (float)M);
        gemm_kernel<1><<<gemm_blocks, 128>>>(p_h,
                                             W2 + (size_t)l * D * D, b2 + (size_t)l * D,
                                             p_scale, p_shift, xout, nullptr, nullptr, M);
    }
}

// round 13
// speedup vs baseline: 1.5031x; 1.1985x over previous
#include <cuda_runtime.h>
#include <cuda_bf16.h>
#include <mma.h>
using namespace nvcuda;

#define D 128
#define MAXN 50176
#define MAXE 524288
#define SCAN_B 1024
#define PIPE 4

typedef unsigned long long u64;
typedef unsigned int u32;

// ---- tc_gemm smem layout (bytes from dynamic smem base) ----
#define BN0_OFF 0
#define BN1_OFF 512
#define ST0_OFF 1024
#define ST1_OFF 1536
#define TILE_OFF 2048
#define LDA 72
#define LDB 136
#define AH_OFF (TILE_OFF)
#define AL_OFF (AH_OFF + 128 * LDA * 2)
#define BH_OFF (AL_OFF + 128 * LDA * 2)
#define BL_OFF (BH_OFF + 64 * LDB * 2)
#define TCSMEM (BL_OFF + 64 * LDB * 2)   // 2048 + 2*18432 + 2*17408 = 73728

// cp.async helpers (agg kernel)
__device__ __forceinline__ void cpa16(u32 dst, const void* src) {
    asm volatile("cp.async.cg.shared.global [%0], [%1], 16;" :: "r"(dst), "l"(src));
}
__device__ __forceinline__ void cpa16_stream(u32 dst, const void* src, u64 pol) {
    asm volatile("cp.async.cg.shared.global.L2::cache_hint [%0], [%1], 16, %2;"
                 :: "r"(dst), "l"(src), "l"(pol));
}
#define CP_COMMIT() asm volatile("cp.async.commit_group;" ::: "memory")
#define CP_WAIT(n)  asm volatile("cp.async.wait_group %0;" :: "n"(n) : "memory")

__device__ __forceinline__ u32 smem_u32(const void* p) {
    u32 a;
    asm("{ .reg .u64 t; cvta.to.shared.u64 t, %1; cvt.u32.u64 %0, t; }" : "=r"(a) : "l"(p));
    return a;
}

// ---- device scratch ----
__device__ float g_agg[MAXN * D];
__device__ float g_h[MAXN * D];
__device__ float g_x1[MAXN * D];
__device__ float g_sum[D];
__device__ float g_sq[D];
__device__ float g_scale[D];
__device__ float g_shift[D];
__device__ int g_cnt[MAXN];
__device__ int g_rowptr[MAXN];
__device__ int g_fill[MAXN];
__device__ int g_perm[MAXE];
__device__ int g_se[MAXE];
__device__ int g_bsum[64];

// ================= CSR build =================
__global__ void hist_kernel(const int* __restrict__ ei, int* __restrict__ cnt, int E) {
    int i = blockIdx.x * blockDim.x + threadIdx.x;
    if (i < E) atomicAdd(&cnt[__ldg(ei + E + i)], 1);
}

__global__ __launch_bounds__(SCAN_B) void scan1_kernel(
    const int* __restrict__ cnt, int* __restrict__ rowptr, int* __restrict__ bsum, int n)
{
    __shared__ int sh[SCAN_B];
    int t = threadIdx.x;
    int i = blockIdx.x * SCAN_B + t;
    int v = (i < n) ? cnt[i] : 0;
    sh[t] = v;
    __syncthreads();
#pragma unroll
    for (int off = 1; off < SCAN_B; off <<= 1) {
        int add = (t >= off) ? sh[t - off] : 0;
        __syncthreads();
        sh[t] += add;
        __syncthreads();
    }
    if (i < n) rowptr[i] = sh[t] - v;
    if (t == SCAN_B - 1) bsum[blockIdx.x] = sh[t];
}

__global__ __launch_bounds__(SCAN_B) void scan23_kernel(
    int* __restrict__ rowptr, int* __restrict__ fill, const int* __restrict__ bsum, int n)
{
    __shared__ int boff_s;
    if (threadIdx.x == 0) {
        int acc = 0;
        for (int b = 0; b < blockIdx.x; b++) acc += bsum[b];
        boff_s = acc;
    }
    __syncthreads();
    int i = blockIdx.x * SCAN_B + threadIdx.x;
    if (i < n) {
        int r = rowptr[i] + boff_s;
        rowptr[i] = r;
        fill[i] = r;
    }
}

__global__ void scatter_kernel(const int* __restrict__ ei, int* __restrict__ fill,
                               int* __restrict__ perm, int* __restrict__ se,
                               int* __restrict__ cnt, int E, int N) {
    int e = blockIdx.x * blockDim.x + threadIdx.x;
    if (e < N) cnt[e] = 0;
    if (e < E) {
        int s = __ldg(ei + e);
        int d = __ldg(ei + E + e);
        int idx = atomicAdd(&fill[d], 1);
        perm[idx] = e;
        se[idx] = s;
    }
}

// ========== aggregate (R11 winner: cp.async pipeline + evict-first ea) ==========
__global__ __launch_bounds__(256) void agg_kernel(
    const float* __restrict__ x, const float* __restrict__ ea,
    const int* __restrict__ rowptr, const int* __restrict__ rowend,
    const int* __restrict__ perm, const int* __restrict__ se,
    float* __restrict__ agg, float* __restrict__ ssum, float* __restrict__ ssq, int N)
{
    __shared__ float4 buf[8][PIPE][2][32];
    if (blockIdx.x == 0 && threadIdx.x < D) {
        ssum[threadIdx.x] = 0.f;
        ssq[threadIdx.x] = 0.f;
    }
    int w = threadIdx.x >> 5;
    int lane = threadIdx.x & 31;
    int v = blockIdx.x * 8 + w;
    if (v >= N) return;
    u64 pol;
    asm("createpolicy.fractional.L2::evict_first.b64 %0, 1.0;" : "=l"(pol));
    int j = __ldg(rowptr + v);
    int end = __ldg(rowend + v);
    int deg = end - j;
    const float4* x4 = (const float4*)x;
    const float4* ea4 = (const float4*)ea;
    float4 acc = __ldg(x4 + (size_t)v * 32 + lane);
    u32 bx = smem_u32(&buf[w][0][0][lane]);
#pragma unroll
    for (int p = 0; p < PIPE; p++) {
        if (p < deg) {
            int e = __ldg(perm + j + p);
            int s = __ldg(se + j + p);
            cpa16(bx + p * 1024, x4 + (size_t)s * 32 + lane);
            cpa16_stream(bx + p * 1024 + 512, ea4 + (size_t)e * 32 + lane, pol);
        }
        CP_COMMIT();
    }
    int slot = 0;
    for (int i = 0; i < deg; i++) {
        int nj = j + i + PIPE;
        bool isu = (nj < end);
        int e = 0, s = 0;
        if (isu) { e = __ldg(perm + nj); s = __ldg(se + nj); }
        CP_WAIT(PIPE - 1);
        float4 xv = buf[w][slot][0][lane];
        float4 ev = buf[w][slot][1][lane];
        if (isu) {
            cpa16(bx + slot * 1024, x4 + (size_t)s * 32 + lane);
            cpa16_stream(bx + slot * 1024 + 512, ea4 + (size_t)e * 32 + lane, pol);
        }
        CP_COMMIT();
        acc.x += fmaxf(xv.x + ev.x, 0.f);
        acc.y += fmaxf(xv.y + ev.y, 0.f);
        acc.z += fmaxf(xv.z + ev.z, 0.f);
        acc.w += fmaxf(xv.w + ev.w, 0.f);
        slot = (slot + 1) & (PIPE - 1);
    }
    asm volatile("cp.async.wait_all;" ::: "memory");
    ((float4*)agg)[(size_t)v * 32 + lane] = acc;
}

// ================= wmma bf16x3-split GEMM =================
// MODE 0: h = A@W + b (write h, accumulate BN stats)
// MODE 1: out = relu( relu(A*scale+shift) @ W + b )
template<int MODE>
__global__ __launch_bounds__(256)
void tc_gemm_kernel(const float* __restrict__ A, const float* __restrict__ W,
                    const float* __restrict__ bias,
                    const float* __restrict__ scale, const float* __restrict__ shift,
                    float* __restrict__ out,
                    float* __restrict__ ssum, float* __restrict__ ssq, int M)
{
    extern __shared__ char sm[];
    int tid = threadIdx.x;
    int wid = tid >> 5;
    int lane = tid & 31;
    int row_base = blockIdx.x * 128;

    float* sc_s = (float*)(sm + BN0_OFF);
    float* sh_s = (float*)(sm + BN1_OFF);
    float* st0  = (float*)(sm + ST0_OFF);
    float* st1  = (float*)(sm + ST1_OFF);
    __nv_bfloat16* Ah = (__nv_bfloat16*)(sm + AH_OFF);
    __nv_bfloat16* Al = (__nv_bfloat16*)(sm + AL_OFF);
    __nv_bfloat16* Bh = (__nv_bfloat16*)(sm + BH_OFF);
    __nv_bfloat16* Bl = (__nv_bfloat16*)(sm + BL_OFF);

    if (tid < D) {
        if (MODE == 1) { sc_s[tid] = __ldg(scale + tid); sh_s[tid] = __ldg(shift + tid); }
        else           { st0[tid] = 0.f; st1[tid] = 0.f; }
    }

    wmma::fragment<wmma::accumulator, 16, 16, 16, float> acc[8];
#pragma unroll
    for (int nt = 0; nt < 8; nt++) wmma::fill_fragment(acc[nt], 0.f);

    const float4* A4 = (const float4*)A;
    const float4* W4 = (const float4*)W;

    for (int hh = 0; hh < 2; hh++) {
        int kb = hh * 64;
        __syncthreads();   // BN/stats init done; prior-phase tile reads done
        // ---- stage A half [128 x 64] as bf16 hi/lo ----
#pragma unroll
        for (int it = 0; it < 8; it++) {
            int idx = it * 256 + tid;      // 0..2047
            int row = idx >> 4;            // 0..127
            int c4  = idx & 15;            // float4 idx within the 64-wide half
            int grow = row_base + row;
            float4 a = make_float4(0.f, 0.f, 0.f, 0.f);
            if (grow < M) {
                a = __ldg(A4 + (size_t)grow * 32 + (kb >> 2) + c4);
                if (MODE == 1) {
                    int gc = kb + c4 * 4;
                    a.x = fmaxf(fmaf(a.x, sc_s[gc + 0], sh_s[gc + 0]), 0.f);
                    a.y = fmaxf(fmaf(a.y, sc_s[gc + 1], sh_s[gc + 1]), 0.f);
                    a.z = fmaxf(fmaf(a.z, sc_s[gc + 2], sh_s[gc + 2]), 0.f);
                    a.w = fmaxf(fmaf(a.w, sc_s[gc + 3], sh_s[gc + 3]), 0.f);
                }
            }
            float v[4] = {a.x, a.y, a.z, a.w};
            unsigned short h[4], l[4];
#pragma unroll
            for (int e = 0; e < 4; e++) {
                __nv_bfloat16 hb = __float2bfloat16(v[e]);
                float hf = __bfloat162float(hb);
                __nv_bfloat16 lb = __float2bfloat16(v[e] - hf);
                h[e] = *reinterpret_cast<unsigned short*>(&hb);
                l[e] = *reinterpret_cast<unsigned short*>(&lb);
            }
            int off = row * LDA + c4 * 4;   // bytes: row*144 + c4*8 -> 8B aligned
            *(uint2*)(Ah + off) = make_uint2((u32)h[0] | ((u32)h[1] << 16),
                                             (u32)h[2] | ((u32)h[3] << 16));
            *(uint2*)(Al + off) = make_uint2((u32)l[0] | ((u32)l[1] << 16),
                                             (u32)l[2] | ((u32)l[3] << 16));
        }
        // ---- stage B = W half [64 x 128] as bf16 hi/lo (row-major, k rows) ----
#pragma unroll
        for (int it = 0; it < 8; it++) {
            int idx = it * 256 + tid;      // 0..2047
            int k  = idx >> 5;             // 0..63
            int n4 = idx & 31;             // float4 idx along n (0..31)
            float4 w = __ldg(W4 + (size_t)(kb + k) * 32 + n4);
            float v[4] = {w.x, w.y, w.z, w.w};
            unsigned short h[4], l[4];
#pragma unroll
            for (int e = 0; e < 4; e++) {
                __nv_bfloat16 hb = __float2bfloat16(v[e]);
                float hf = __bfloat162float(hb);
                __nv_bfloat16 lb = __float2bfloat16(v[e] - hf);
                h[e] = *reinterpret_cast<unsigned short*>(&hb);
                l[e] = *reinterpret_cast<unsigned short*>(&lb);
            }
            int off = k * LDB + n4 * 4;    // bytes: k*272 + n4*8 -> 8B aligned
            *(uint2*)(Bh + off) = make_uint2((u32)h[0] | ((u32)h[1] << 16),
                                             (u32)h[2] | ((u32)h[3] << 16));
            *(uint2*)(Bl + off) = make_uint2((u32)l[0] | ((u32)l[1] << 16),
                                             (u32)l[2] | ((u32)l[3] << 16));
        }
        __syncthreads();
        // ---- mma: each warp = 16 rows x 128 cols, 3-pass split ----
        int wrow = wid * 16;
        wmma::fragment<wmma::matrix_a, 16, 16, 16, __nv_bfloat16, wmma::row_major> fah, fal;
        wmma::fragment<wmma::matrix_b, 16, 16, 16, __nv_bfloat16, wmma::row_major> fbh, fbl;
#pragma unroll
        for (int kc = 0; kc < 4; kc++) {
            wmma::load_matrix_sync(fah, Ah + wrow * LDA + kc * 16, LDA);
            wmma::load_matrix_sync(fal, Al + wrow * LDA + kc * 16, LDA);
#pragma unroll
            for (int nt = 0; nt < 8; nt++) {
                wmma::load_matrix_sync(fbh, Bh + (kc * 16) * LDB + nt * 16, LDB);
                wmma::load_matrix_sync(fbl, Bl + (kc * 16) * LDB + nt * 16, LDB);
                wmma::mma_sync(acc[nt], fah, fbh, acc[nt]);
                wmma::mma_sync(acc[nt], fah, fbl, acc[nt]);
                wmma::mma_sync(acc[nt], fal, fbh, acc[nt]);
            }
        }
    }
    __syncthreads();   // all tile reads done; reuse tile smem for C staging

    // ---- epilogue: per-warp C tile [16 x 128] staged in smem ----
    float* Cw = (float*)(sm + TILE_OFF) + wid * 16 * 132;
#pragma unroll
    for (int nt = 0; nt < 8; nt++)
        wmma::store_matrix_sync(Cw + nt * 16, acc[nt], 132, wmma::mem_row_major);
    __syncwarp();

    float bv[4];
#pragma unroll
    for (int e = 0; e < 4; e++) bv[e] = __ldg(bias + lane * 4 + e);
    float cs[4] = {0.f, 0.f, 0.f, 0.f}, cq[4] = {0.f, 0.f, 0.f, 0.f};
#pragma unroll
    for (int i = 0; i < 16; i++) {
        int row = row_base + wid * 16 + i;
        if (row < M) {
            float4 o = *(float4*)(Cw + i * 132 + lane * 4);
            o.x += bv[0]; o.y += bv[1]; o.z += bv[2]; o.w += bv[3];
            if (MODE == 1) {
                o.x = fmaxf(o.x, 0.f); o.y = fmaxf(o.y, 0.f);
                o.z = fmaxf(o.z, 0.f); o.w = fmaxf(o.w, 0.f);
            }
            *(float4*)(out + (size_t)row * D + lane * 4) = o;
            if (MODE == 0) {
                cs[0] += o.x; cq[0] += o.x * o.x;
                cs[1] += o.y; cq[1] += o.y * o.y;
                cs[2] += o.z; cq[2] += o.z * o.z;
                cs[3] += o.w; cq[3] += o.w * o.w;
            }
        }
    }
    if (MODE == 0) {
#pragma unroll
        for (int e = 0; e < 4; e++) {
            atomicAdd(&st0[lane * 4 + e], cs[e]);
            atomicAdd(&st1[lane * 4 + e], cq[e]);
        }
        __syncthreads();
        if (tid < D) {
            atomicAdd(&ssum[tid], st0[tid]);
            atomicAdd(&ssq[tid], st1[tid]);
        }
    }
}

// ---- fold BN stats into per-feature scale/shift ----
__global__ void finalize_kernel(const float* __restrict__ ssum, const float* __restrict__ ssq,
                                const float* __restrict__ gamma, const float* __restrict__ beta,
                                float* __restrict__ scale, float* __restrict__ shift, float invN)
{
    int i = threadIdx.x;
    float m = ssum[i] * invN;
    float v = fmaf(ssq[i], invN, -m * m);
    float r = rsqrtf(v + 1e-5f);
    float sc = r * __ldg(gamma + i);
    scale[i] = sc;
    shift[i] = fmaf(-m, sc, __ldg(beta + i));
}

extern "C" void kernel_launch(void* const* d_in, const int* in_sizes, int n_in,
                              void* d_out, int out_size) {
    const float* x     = (const float*)d_in[0];
    const int*   ei    = (const int*)d_in[1];
    const float* ea    = (const float*)d_in[2];
    const float* W1    = (const float*)d_in[3];
    const float* b1    = (const float*)d_in[4];
    const float* gamma = (const float*)d_in[5];
    const float* beta  = (const float*)d_in[6];
    const float* W2    = (const float*)d_in[7];
    const float* b2    = (const float*)d_in[8];

    int M = in_sizes[0] / D;
    int E = in_sizes[2] / D;
    int L = in_sizes[3] / (D * D);

    float *p_agg, *p_h, *p_x1, *p_sum, *p_sq, *p_scale, *p_shift;
    int *p_cnt, *p_rowptr, *p_fill, *p_perm, *p_se, *p_bsum;
    cudaGetSymbolAddress((void**)&p_agg,   g_agg);
    cudaGetSymbolAddress((void**)&p_h,     g_h);
    cudaGetSymbolAddress((void**)&p_x1,    g_x1);
    cudaGetSymbolAddress((void**)&p_sum,   g_sum);
    cudaGetSymbolAddress((void**)&p_sq,    g_sq);
    cudaGetSymbolAddress((void**)&p_scale, g_scale);
    cudaGetSymbolAddress((void**)&p_shift, g_shift);
    cudaGetSymbolAddress((void**)&p_cnt,    g_cnt);
    cudaGetSymbolAddress((void**)&p_rowptr, g_rowptr);
    cudaGetSymbolAddress((void**)&p_fill,   g_fill);
    cudaGetSymbolAddress((void**)&p_perm,   g_perm);
    cudaGetSymbolAddress((void**)&p_se,     g_se);
    cudaGetSymbolAddress((void**)&p_bsum,   g_bsum);

    cudaFuncSetAttribute(tc_gemm_kernel<0>, cudaFuncAttributeMaxDynamicSharedMemorySize, TCSMEM);
    cudaFuncSetAttribute(tc_gemm_kernel<1>, cudaFuncAttributeMaxDynamicSharedMemorySize, TCSMEM);

    int gemm_blocks = (M + 127) / 128;
    int eb = (E + 255) / 256;
    int nbscan = (M + SCAN_B - 1) / SCAN_B;
    int agg_blocks = (M + 7) / 8;

    hist_kernel<<<eb, 256>>>(ei, p_cnt, E);
    scan1_kernel<<<nbscan, SCAN_B>>>(p_cnt, p_rowptr, p_bsum, M);
    scan23_kernel<<<nbscan, SCAN_B>>>(p_rowptr, p_fill, p_bsum, M);
    scatter_kernel<<<eb, 256>>>(ei, p_fill, p_perm, p_se, p_cnt, E, M);

    for (int l = 0; l < L; l++) {
        const float* xin = (l == 0) ? x : p_x1;
        float* xout = (l == L - 1) ? (float*)d_out : p_x1;

        agg_kernel<<<agg_blocks, 256>>>(xin, ea, p_rowptr, p_fill, p_perm, p_se,
                                        p_agg, p_sum, p_sq, M);
        tc_gemm_kernel<0><<<gemm_blocks, 256, TCSMEM>>>(p_agg,
            W1 + (size_t)l * D * D, b1 + (size_t)l * D,
            nullptr, nullptr, p_h, p_sum, p_sq, M);
        finalize_kernel<<<1, D>>>(p_sum, p_sq, gamma + (size_t)l * D, beta + (size_t)l * D,
                                  p_scale, p_shift, 1.0f / (float)M);
        tc_gemm_kernel<1><<<gemm_blocks, 256, TCSMEM>>>(p_h,
            W2 + (size_t)l * D * D, b2 + (size_t)l * D,
            p_scale, p_shift, xout, nullptr, nullptr, M);
    }
}

// round 14
// speedup vs baseline: 1.5224x; 1.0129x over previous
#include <cuda_runtime.h>
#include <cuda_bf16.h>
#include <mma.h>
using namespace nvcuda;

#define D 128
#define MAXN 50176
#define MAXE 524288
#define SCAN_B 1024
#define PIPE 4

typedef unsigned long long u64;
typedef unsigned int u32;

// ---- tc_gemm smem layout (bytes from dynamic smem base) ----
#define BN0_OFF 0
#define BN1_OFF 512
#define ST0_OFF 1024
#define ST1_OFF 1536
#define TILE_OFF 2048
#define LDA 72
#define LDB 136
#define AH_OFF (TILE_OFF)
#define AL_OFF (AH_OFF + 128 * LDA * 2)
#define BH_OFF (AL_OFF + 128 * LDA * 2)
#define BL_OFF (BH_OFF + 64 * LDB * 2)
#define TCSMEM (BL_OFF + 64 * LDB * 2)   // 73728

// cp.async helpers (agg kernel)
__device__ __forceinline__ void cpa16(u32 dst, const void* src) {
    asm volatile("cp.async.cg.shared.global [%0], [%1], 16;" :: "r"(dst), "l"(src));
}
__device__ __forceinline__ void cpa16_stream(u32 dst, const void* src, u64 pol) {
    asm volatile("cp.async.cg.shared.global.L2::cache_hint [%0], [%1], 16, %2;"
                 :: "r"(dst), "l"(src), "l"(pol));
}
#define CP_COMMIT() asm volatile("cp.async.commit_group;" ::: "memory")
#define CP_WAIT(n)  asm volatile("cp.async.wait_group %0;" :: "n"(n) : "memory")

__device__ __forceinline__ u32 smem_u32(const void* p) {
    u32 a;
    asm("{ .reg .u64 t; cvta.to.shared.u64 t, %1; cvt.u32.u64 %0, t; }" : "=r"(a) : "l"(p));
    return a;
}

// ---- device scratch ----
__device__ float g_agg[MAXN * D];
__device__ float g_h[MAXN * D];
__device__ float g_x1[MAXN * D];
__device__ float g_sum[D];
__device__ float g_sq[D];
__device__ int g_cnt[MAXN];      // zero at load; re-zeroed by scatter each launch
__device__ int g_rowptr[MAXN];
__device__ int g_fill[MAXN];
__device__ int g_perm[MAXE];
__device__ int g_se[MAXE];
__device__ int g_bsum[64];
__device__ int g_ready;          // zero at load; re-zeroed by scatter each launch

// ================= CSR build (3 kernels) =================
__global__ void hist_kernel(const int* __restrict__ ei, int* __restrict__ cnt, int E) {
    int i = blockIdx.x * blockDim.x + threadIdx.x;
    if (i < E) atomicAdd(&cnt[__ldg(ei + E + i)], 1);
}

// single-pass scan: local block scan + grid quiescence on atomic counter.
// All blocks (<=49) are co-resident (148 SMs, 1024 thr/block), so the spin
// cannot deadlock. scatter_kernel resets *ready for the next graph replay.
__global__ __launch_bounds__(SCAN_B) void scan_kernel(
    const int* __restrict__ cnt, int* __restrict__ rowptr, int* __restrict__ fill,
    int* __restrict__ bsum, int* __restrict__ ready, int n)
{
    __shared__ int sh[SCAN_B];
    __shared__ int boff_s;
    int t = threadIdx.x;
    int b = blockIdx.x;
    int i = b * SCAN_B + t;
    int v = (i < n) ? cnt[i] : 0;
    sh[t] = v;
    __syncthreads();
#pragma unroll
    for (int off = 1; off < SCAN_B; off <<= 1) {
        int add = (t >= off) ? sh[t - off] : 0;
        __syncthreads();
        sh[t] += add;
        __syncthreads();
    }
    if (t == SCAN_B - 1) {
        bsum[b] = sh[t];
        __threadfence();
        atomicAdd(ready, 1);
    }
    if (t == 0) {
        while (atomicAdd(ready, 0) < gridDim.x) { }
        __threadfence();
        int acc = 0;
        for (int k = 0; k < b; k++) acc += bsum[k];
        boff_s = acc;
    }
    __syncthreads();
    if (i < n) {
        int r = sh[t] - v + boff_s;
        rowptr[i] = r;
        fill[i] = r;
    }
}

__global__ void scatter_kernel(const int* __restrict__ ei, int* __restrict__ fill,
                               int* __restrict__ perm, int* __restrict__ se,
                               int* __restrict__ cnt, int* __restrict__ ready,
                               int E, int N) {
    int e = blockIdx.x * blockDim.x + threadIdx.x;
    if (e < N) cnt[e] = 0;
    if (e == 0) *ready = 0;
    if (e < E) {
        int s = __ldg(ei + e);
        int d = __ldg(ei + E + e);
        int idx = atomicAdd(&fill[d], 1);
        perm[idx] = e;
        se[idx] = s;
    }
}

// ========== aggregate (R11 winner: cp.async pipeline + evict-first ea) ==========
__global__ __launch_bounds__(256) void agg_kernel(
    const float* __restrict__ x, const float* __restrict__ ea,
    const int* __restrict__ rowptr, const int* __restrict__ rowend,
    const int* __restrict__ perm, const int* __restrict__ se,
    float* __restrict__ agg, float* __restrict__ ssum, float* __restrict__ ssq, int N)
{
    __shared__ float4 buf[8][PIPE][2][32];
    if (blockIdx.x == 0 && threadIdx.x < D) {
        ssum[threadIdx.x] = 0.f;
        ssq[threadIdx.x] = 0.f;
    }
    int w = threadIdx.x >> 5;
    int lane = threadIdx.x & 31;
    int v = blockIdx.x * 8 + w;
    if (v >= N) return;
    u64 pol;
    asm("createpolicy.fractional.L2::evict_first.b64 %0, 1.0;" : "=l"(pol));
    int j = __ldg(rowptr + v);
    int end = __ldg(rowend + v);
    int deg = end - j;
    const float4* x4 = (const float4*)x;
    const float4* ea4 = (const float4*)ea;
    float4 acc = __ldg(x4 + (size_t)v * 32 + lane);
    u32 bx = smem_u32(&buf[w][0][0][lane]);
#pragma unroll
    for (int p = 0; p < PIPE; p++) {
        if (p < deg) {
            int e = __ldg(perm + j + p);
            int s = __ldg(se + j + p);
            cpa16(bx + p * 1024, x4 + (size_t)s * 32 + lane);
            cpa16_stream(bx + p * 1024 + 512, ea4 + (size_t)e * 32 + lane, pol);
        }
        CP_COMMIT();
    }
    int slot = 0;
    for (int i = 0; i < deg; i++) {
        int nj = j + i + PIPE;
        bool isu = (nj < end);
        int e = 0, s = 0;
        if (isu) { e = __ldg(perm + nj); s = __ldg(se + nj); }
        CP_WAIT(PIPE - 1);
        float4 xv = buf[w][slot][0][lane];
        float4 ev = buf[w][slot][1][lane];
        if (isu) {
            cpa16(bx + slot * 1024, x4 + (size_t)s * 32 + lane);
            cpa16_stream(bx + slot * 1024 + 512, ea4 + (size_t)e * 32 + lane, pol);
        }
        CP_COMMIT();
        acc.x += fmaxf(xv.x + ev.x, 0.f);
        acc.y += fmaxf(xv.y + ev.y, 0.f);
        acc.z += fmaxf(xv.z + ev.z, 0.f);
        acc.w += fmaxf(xv.w + ev.w, 0.f);
        slot = (slot + 1) & (PIPE - 1);
    }
    asm volatile("cp.async.wait_all;" ::: "memory");
    ((float4*)agg)[(size_t)v * 32 + lane] = acc;
}

// ================= wmma bf16x3-split GEMM =================
// MODE 0: h = A@W + b (write h, accumulate BN stats into ssum/ssq)
// MODE 1: out = relu( relu(A*scale+shift) @ W + b ); scale/shift computed
//         in-prologue from raw stats (gamma,beta,invN) -- no finalize kernel.
template<int MODE>
__global__ __launch_bounds__(256)
void tc_gemm_kernel(const float* __restrict__ A, const float* __restrict__ W,
                    const float* __restrict__ bias,
                    const float* __restrict__ gamma, const float* __restrict__ beta,
                    float invN,
                    float* __restrict__ out,
                    float* __restrict__ ssum, float* __restrict__ ssq, int M)
{
    extern __shared__ char sm[];
    int tid = threadIdx.x;
    int wid = tid >> 5;
    int lane = tid & 31;
    int row_base = blockIdx.x * 128;

    float* sc_s = (float*)(sm + BN0_OFF);
    float* sh_s = (float*)(sm + BN1_OFF);
    float* st0  = (float*)(sm + ST0_OFF);
    float* st1  = (float*)(sm + ST1_OFF);
    __nv_bfloat16* Ah = (__nv_bfloat16*)(sm + AH_OFF);
    __nv_bfloat16* Al = (__nv_bfloat16*)(sm + AL_OFF);
    __nv_bfloat16* Bh = (__nv_bfloat16*)(sm + BH_OFF);
    __nv_bfloat16* Bl = (__nv_bfloat16*)(sm + BL_OFF);

    if (tid < D) {
        if (MODE == 1) {
            float m = __ldg(ssum + tid) * invN;
            float var = fmaf(__ldg(ssq + tid), invN, -m * m);
            float r = rsqrtf(var + 1e-5f);
            float sc = r * __ldg(gamma + tid);
            sc_s[tid] = sc;
            sh_s[tid] = fmaf(-m, sc, __ldg(beta + tid));
        } else {
            st0[tid] = 0.f;
            st1[tid] = 0.f;
        }
    }

    wmma::fragment<wmma::accumulator, 16, 16, 16, float> acc[8];
#pragma unroll
    for (int nt = 0; nt < 8; nt++) wmma::fill_fragment(acc[nt], 0.f);

    const float4* A4 = (const float4*)A;
    const float4* W4 = (const float4*)W;

    for (int hh = 0; hh < 2; hh++) {
        int kb = hh * 64;
        __syncthreads();
        // ---- stage A half [128 x 64] as bf16 hi/lo ----
#pragma unroll
        for (int it = 0; it < 8; it++) {
            int idx = it * 256 + tid;
            int row = idx >> 4;
            int c4  = idx & 15;
            int grow = row_base + row;
            float4 a = make_float4(0.f, 0.f, 0.f, 0.f);
            if (grow < M) {
                a = __ldg(A4 + (size_t)grow * 32 + (kb >> 2) + c4);
                if (MODE == 1) {
                    int gc = kb + c4 * 4;
                    a.x = fmaxf(fmaf(a.x, sc_s[gc + 0], sh_s[gc + 0]), 0.f);
                    a.y = fmaxf(fmaf(a.y, sc_s[gc + 1], sh_s[gc + 1]), 0.f);
                    a.z = fmaxf(fmaf(a.z, sc_s[gc + 2], sh_s[gc + 2]), 0.f);
                    a.w = fmaxf(fmaf(a.w, sc_s[gc + 3], sh_s[gc + 3]), 0.f);
                }
            }
            float v[4] = {a.x, a.y, a.z, a.w};
            unsigned short h[4], l[4];
#pragma unroll
            for (int e = 0; e < 4; e++) {
                __nv_bfloat16 hb = __float2bfloat16(v[e]);
                float hf = __bfloat162float(hb);
                __nv_bfloat16 lb = __float2bfloat16(v[e] - hf);
                h[e] = *reinterpret_cast<unsigned short*>(&hb);
                l[e] = *reinterpret_cast<unsigned short*>(&lb);
            }
            int off = row * LDA + c4 * 4;
            *(uint2*)(Ah + off) = make_uint2((u32)h[0] | ((u32)h[1] << 16),
                                             (u32)h[2] | ((u32)h[3] << 16));
            *(uint2*)(Al + off) = make_uint2((u32)l[0] | ((u32)l[1] << 16),
                                             (u32)l[2] | ((u32)l[3] << 16));
        }
        // ---- stage B = W half [64 x 128] as bf16 hi/lo ----
#pragma unroll
        for (int it = 0; it < 8; it++) {
            int idx = it * 256 + tid;
            int k  = idx >> 5;
            int n4 = idx & 31;
            float4 w = __ldg(W4 + (size_t)(kb + k) * 32 + n4);
            float v[4] = {w.x, w.y, w.z, w.w};
            unsigned short h[4], l[4];
#pragma unroll
            for (int e = 0; e < 4; e++) {
                __nv_bfloat16 hb = __float2bfloat16(v[e]);
                float hf = __bfloat162float(hb);
                __nv_bfloat16 lb = __float2bfloat16(v[e] - hf);
                h[e] = *reinterpret_cast<unsigned short*>(&hb);
                l[e] = *reinterpret_cast<unsigned short*>(&lb);
            }
            int off = k * LDB + n4 * 4;
            *(uint2*)(Bh + off) = make_uint2((u32)h[0] | ((u32)h[1] << 16),
                                             (u32)h[2] | ((u32)h[3] << 16));
            *(uint2*)(Bl + off) = make_uint2((u32)l[0] | ((u32)l[1] << 16),
                                             (u32)l[2] | ((u32)l[3] << 16));
        }
        __syncthreads();
        // ---- mma: each warp = 16 rows x 128 cols, 3-pass split ----
        int wrow = wid * 16;
        wmma::fragment<wmma::matrix_a, 16, 16, 16, __nv_bfloat16, wmma::row_major> fah, fal;
        wmma::fragment<wmma::matrix_b, 16, 16, 16, __nv_bfloat16, wmma::row_major> fbh, fbl;
#pragma unroll
        for (int kc = 0; kc < 4; kc++) {
            wmma::load_matrix_sync(fah, Ah + wrow * LDA + kc * 16, LDA);
            wmma::load_matrix_sync(fal, Al + wrow * LDA + kc * 16, LDA);
#pragma unroll
            for (int nt = 0; nt < 8; nt++) {
                wmma::load_matrix_sync(fbh, Bh + (kc * 16) * LDB + nt * 16, LDB);
                wmma::load_matrix_sync(fbl, Bl + (kc * 16) * LDB + nt * 16, LDB);
                wmma::mma_sync(acc[nt], fah, fbh, acc[nt]);
                wmma::mma_sync(acc[nt], fah, fbl, acc[nt]);
                wmma::mma_sync(acc[nt], fal, fbh, acc[nt]);
            }
        }
    }
    __syncthreads();   // all tile reads done; reuse tile smem for C staging

    // ---- epilogue ----
    float* Cw = (float*)(sm + TILE_OFF) + wid * 16 * 132;
#pragma unroll
    for (int nt = 0; nt < 8; nt++)
        wmma::store_matrix_sync(Cw + nt * 16, acc[nt], 132, wmma::mem_row_major);
    __syncwarp();

    float bv[4];
#pragma unroll
    for (int e = 0; e < 4; e++) bv[e] = __ldg(bias + lane * 4 + e);
    float cs[4] = {0.f, 0.f, 0.f, 0.f}, cq[4] = {0.f, 0.f, 0.f, 0.f};
#pragma unroll
    for (int i = 0; i < 16; i++) {
        int row = row_base + wid * 16 + i;
        if (row < M) {
            float4 o = *(float4*)(Cw + i * 132 + lane * 4);
            o.x += bv[0]; o.y += bv[1]; o.z += bv[2]; o.w += bv[3];
            if (MODE == 1) {
                o.x = fmaxf(o.x, 0.f); o.y = fmaxf(o.y, 0.f);
                o.z = fmaxf(o.z, 0.f); o.w = fmaxf(o.w, 0.f);
            }
            *(float4*)(out + (size_t)row * D + lane * 4) = o;
            if (MODE == 0) {
                cs[0] += o.x; cq[0] += o.x * o.x;
                cs[1] += o.y; cq[1] += o.y * o.y;
                cs[2] += o.z; cq[2] += o.z * o.z;
                cs[3] += o.w; cq[3] += o.w * o.w;
            }
        }
    }
    if (MODE == 0) {
#pragma unroll
        for (int e = 0; e < 4; e++) {
            atomicAdd(&st0[lane * 4 + e], cs[e]);
            atomicAdd(&st1[lane * 4 + e], cq[e]);
        }
        __syncthreads();
        if (tid < D) {
            atomicAdd(&ssum[tid], st0[tid]);
            atomicAdd(&ssq[tid], st1[tid]);
        }
    }
}

extern "C" void kernel_launch(void* const* d_in, const int* in_sizes, int n_in,
                              void* d_out, int out_size) {
    const float* x     = (const float*)d_in[0];
    const int*   ei    = (const int*)d_in[1];
    const float* ea    = (const float*)d_in[2];
    const float* W1    = (const float*)d_in[3];
    const float* b1    = (const float*)d_in[4];
    const float* gamma = (const float*)d_in[5];
    const float* beta  = (const float*)d_in[6];
    const float* W2    = (const float*)d_in[7];
    const float* b2    = (const float*)d_in[8];

    int M = in_sizes[0] / D;
    int E = in_sizes[2] / D;
    int L = in_sizes[3] / (D * D);
    float invN = 1.0f / (float)M;

    float *p_agg, *p_h, *p_x1, *p_sum, *p_sq;
    int *p_cnt, *p_rowptr, *p_fill, *p_perm, *p_se, *p_bsum, *p_ready;
    cudaGetSymbolAddress((void**)&p_agg,   g_agg);
    cudaGetSymbolAddress((void**)&p_h,     g_h);
    cudaGetSymbolAddress((void**)&p_x1,    g_x1);
    cudaGetSymbolAddress((void**)&p_sum,   g_sum);
    cudaGetSymbolAddress((void**)&p_sq,    g_sq);
    cudaGetSymbolAddress((void**)&p_cnt,    g_cnt);
    cudaGetSymbolAddress((void**)&p_rowptr, g_rowptr);
    cudaGetSymbolAddress((void**)&p_fill,   g_fill);
    cudaGetSymbolAddress((void**)&p_perm,   g_perm);
    cudaGetSymbolAddress((void**)&p_se,     g_se);
    cudaGetSymbolAddress((void**)&p_bsum,   g_bsum);
    cudaGetSymbolAddress((void**)&p_ready,  g_ready);

    cudaFuncSetAttribute(tc_gemm_kernel<0>, cudaFuncAttributeMaxDynamicSharedMemorySize, TCSMEM);
    cudaFuncSetAttribute(tc_gemm_kernel<1>, cudaFuncAttributeMaxDynamicSharedMemorySize, TCSMEM);

    int gemm_blocks = (M + 127) / 128;
    int eb = (E + 255) / 256;
    int nbscan = (M + SCAN_B - 1) / SCAN_B;
    int agg_blocks = (M + 7) / 8;

    // ---- build CSR once: 3 launches (hist, scan, scatter) ----
    hist_kernel<<<eb, 256>>>(ei, p_cnt, E);
    scan_kernel<<<nbscan, SCAN_B>>>(p_cnt, p_rowptr, p_fill, p_bsum, p_ready, M);
    scatter_kernel<<<eb, 256>>>(ei, p_fill, p_perm, p_se, p_cnt, p_ready, E, M);

    for (int l = 0; l < L; l++) {
        const float* xin = (l == 0) ? x : p_x1;
        float* xout = (l == L - 1) ? (float*)d_out : p_x1;

        agg_kernel<<<agg_blocks, 256>>>(xin, ea, p_rowptr, p_fill, p_perm, p_se,
                                        p_agg, p_sum, p_sq, M);
        tc_gemm_kernel<0><<<gemm_blocks, 256, TCSMEM>>>(p_agg,
            W1 + (size_t)l * D * D, b1 + (size_t)l * D,
            nullptr, nullptr, 0.f, p_h, p_sum, p_sq, M);
        tc_gemm_kernel<1><<<gemm_blocks, 256, TCSMEM>>>(p_h,
            W2 + (size_t)l * D * D, b2 + (size_t)l * D,
            gamma + (size_t)l * D, beta + (size_t)l * D, invN,
            xout, p_sum, p_sq, M);
    }
}

// round 15
// speedup vs baseline: 2.0188x; 1.3261x over previous
#include <cuda_runtime.h>
#include <cuda_fp16.h>
#include <mma.h>
using namespace nvcuda;

#define D 128
#define MAXN 50176
#define MAXE 524288
#define SCAN_B 1024
#define PIPE 4

typedef unsigned long long u64;
typedef unsigned int u32;

// ---- tc_gemm smem layout (bytes from dynamic smem base) ----
#define BN0_OFF 0
#define BN1_OFF 512
#define ST0_OFF 1024
#define ST1_OFF 1536
#define TILE_OFF 2048
#define LDA 72
#define LDB 136
#define AH_OFF (TILE_OFF)
#define BH_OFF (AH_OFF + 128 * LDA * 2)
#define BL_OFF (BH_OFF + 64 * LDB * 2)
// staging ends at 55296; C epilogue staging needs 2048+67584=69632
#define TCSMEM 69632

// cp.async helpers (agg kernel)
__device__ __forceinline__ void cpa16(u32 dst, const void* src) {
    asm volatile("cp.async.cg.shared.global [%0], [%1], 16;" :: "r"(dst), "l"(src));
}
__device__ __forceinline__ void cpa16_stream(u32 dst, const void* src, u64 pol) {
    asm volatile("cp.async.cg.shared.global.L2::cache_hint [%0], [%1], 16, %2;"
                 :: "r"(dst), "l"(src), "l"(pol));
}
#define CP_COMMIT() asm volatile("cp.async.commit_group;" ::: "memory")
#define CP_WAIT(n)  asm volatile("cp.async.wait_group %0;" :: "n"(n) : "memory")

__device__ __forceinline__ u32 smem_u32(const void* p) {
    u32 a;
    asm("{ .reg .u64 t; cvta.to.shared.u64 t, %1; cvt.u32.u64 %0, t; }" : "=r"(a) : "l"(p));
    return a;
}

// ---- device scratch ----
__device__ float g_agg[MAXN * D];
__device__ float g_h[MAXN * D];
__device__ float g_x1[MAXN * D];
__device__ float g_sum[D];
__device__ float g_sq[D];
__device__ int g_cnt[MAXN];      // zero at load; re-zeroed by scatter each launch
__device__ int g_rowptr[MAXN];
__device__ int g_fill[MAXN];
__device__ int g_perm[MAXE];
__device__ int g_se[MAXE];
__device__ int g_bsum[64];
__device__ int g_ready;          // zero at load; re-zeroed by scatter each launch

// ================= CSR build (3 kernels) =================
__global__ void hist_kernel(const int* __restrict__ ei, int* __restrict__ cnt, int E) {
    int i = blockIdx.x * blockDim.x + threadIdx.x;
    if (i < E) atomicAdd(&cnt[__ldg(ei + E + i)], 1);
}

// single-pass scan: local block scan + grid quiescence on atomic counter.
// All blocks (<=49) are co-resident, so the spin cannot deadlock.
__global__ __launch_bounds__(SCAN_B) void scan_kernel(
    const int* __restrict__ cnt, int* __restrict__ rowptr, int* __restrict__ fill,
    int* __restrict__ bsum, int* __restrict__ ready, int n)
{
    __shared__ int sh[SCAN_B];
    __shared__ int boff_s;
    int t = threadIdx.x;
    int b = blockIdx.x;
    int i = b * SCAN_B + t;
    int v = (i < n) ? cnt[i] : 0;
    sh[t] = v;
    __syncthreads();
#pragma unroll
    for (int off = 1; off < SCAN_B; off <<= 1) {
        int add = (t >= off) ? sh[t - off] : 0;
        __syncthreads();
        sh[t] += add;
        __syncthreads();
    }
    if (t == SCAN_B - 1) {
        bsum[b] = sh[t];
        __threadfence();
        atomicAdd(ready, 1);
    }
    if (t == 0) {
        while (atomicAdd(ready, 0) < gridDim.x) { }
        __threadfence();
        int acc = 0;
        for (int k = 0; k < b; k++) acc += bsum[k];
        boff_s = acc;
    }
    __syncthreads();
    if (i < n) {
        int r = sh[t] - v + boff_s;
        rowptr[i] = r;
        fill[i] = r;
    }
}

__global__ void scatter_kernel(const int* __restrict__ ei, int* __restrict__ fill,
                               int* __restrict__ perm, int* __restrict__ se,
                               int* __restrict__ cnt, int* __restrict__ ready,
                               int E, int N) {
    int e = blockIdx.x * blockDim.x + threadIdx.x;
    if (e < N) cnt[e] = 0;
    if (e == 0) *ready = 0;
    if (e < E) {
        int s = __ldg(ei + e);
        int d = __ldg(ei + E + e);
        int idx = atomicAdd(&fill[d], 1);
        perm[idx] = e;
        se[idx] = s;
    }
}

// ========== aggregate (cp.async pipeline + evict-first ea; near DRAM roofline) ==========
__global__ __launch_bounds__(256) void agg_kernel(
    const float* __restrict__ x, const float* __restrict__ ea,
    const int* __restrict__ rowptr, const int* __restrict__ rowend,
    const int* __restrict__ perm, const int* __restrict__ se,
    float* __restrict__ agg, float* __restrict__ ssum, float* __restrict__ ssq, int N)
{
    __shared__ float4 buf[8][PIPE][2][32];
    if (blockIdx.x == 0 && threadIdx.x < D) {
        ssum[threadIdx.x] = 0.f;
        ssq[threadIdx.x] = 0.f;
    }
    int w = threadIdx.x >> 5;
    int lane = threadIdx.x & 31;
    int v = blockIdx.x * 8 + w;
    if (v >= N) return;
    u64 pol;
    asm("createpolicy.fractional.L2::evict_first.b64 %0, 1.0;" : "=l"(pol));
    int j = __ldg(rowptr + v);
    int end = __ldg(rowend + v);
    int deg = end - j;
    const float4* x4 = (const float4*)x;
    const float4* ea4 = (const float4*)ea;
    float4 acc = __ldg(x4 + (size_t)v * 32 + lane);
    u32 bx = smem_u32(&buf[w][0][0][lane]);
#pragma unroll
    for (int p = 0; p < PIPE; p++) {
        if (p < deg) {
            int e = __ldg(perm + j + p);
            int s = __ldg(se + j + p);
            cpa16(bx + p * 1024, x4 + (size_t)s * 32 + lane);
            cpa16_stream(bx + p * 1024 + 512, ea4 + (size_t)e * 32 + lane, pol);
        }
        CP_COMMIT();
    }
    int slot = 0;
    for (int i = 0; i < deg; i++) {
        int nj = j + i + PIPE;
        bool isu = (nj < end);
        int e = 0, s = 0;
        if (isu) { e = __ldg(perm + nj); s = __ldg(se + nj); }
        CP_WAIT(PIPE - 1);
        float4 xv = buf[w][slot][0][lane];
        float4 ev = buf[w][slot][1][lane];
        if (isu) {
            cpa16(bx + slot * 1024, x4 + (size_t)s * 32 + lane);
            cpa16_stream(bx + slot * 1024 + 512, ea4 + (size_t)e * 32 + lane, pol);
        }
        CP_COMMIT();
        acc.x += fmaxf(xv.x + ev.x, 0.f);
        acc.y += fmaxf(xv.y + ev.y, 0.f);
        acc.z += fmaxf(xv.z + ev.z, 0.f);
        acc.w += fmaxf(xv.w + ev.w, 0.f);
        slot = (slot + 1) & (PIPE - 1);
    }
    asm volatile("cp.async.wait_all;" ::: "memory");
    ((float4*)agg)[(size_t)v * 32 + lane] = acc;
}

// ================= wmma fp16 2-pass GEMM =================
// A staged as single fp16 (rounding ~2^-11); W split fp16 hi/lo.
// D = Ah@Wh + Ah@Wl, f32 accumulate. Error ~2-5e-4 << 1e-3.
// MODE 0: h = A@W + b (write h, accumulate BN stats)
// MODE 1: out = relu( relu(A*scale+shift) @ W + b ); scale/shift from raw stats.
template<int MODE>
__global__ __launch_bounds__(256)
void tc_gemm_kernel(const float* __restrict__ A, const float* __restrict__ W,
                    const float* __restrict__ bias,
                    const float* __restrict__ gamma, const float* __restrict__ beta,
                    float invN,
                    float* __restrict__ out,
                    float* __restrict__ ssum, float* __restrict__ ssq, int M)
{
    extern __shared__ char sm[];
    int tid = threadIdx.x;
    int wid = tid >> 5;
    int lane = tid & 31;
    int row_base = blockIdx.x * 128;

    float* sc_s = (float*)(sm + BN0_OFF);
    float* sh_s = (float*)(sm + BN1_OFF);
    float* st0  = (float*)(sm + ST0_OFF);
    float* st1  = (float*)(sm + ST1_OFF);
    __half* Ah = (__half*)(sm + AH_OFF);
    __half* Bh = (__half*)(sm + BH_OFF);
    __half* Bl = (__half*)(sm + BL_OFF);

    if (tid < D) {
        if (MODE == 1) {
            float m = __ldg(ssum + tid) * invN;
            float var = fmaf(__ldg(ssq + tid), invN, -m * m);
            float r = rsqrtf(var + 1e-5f);
            float sc = r * __ldg(gamma + tid);
            sc_s[tid] = sc;
            sh_s[tid] = fmaf(-m, sc, __ldg(beta + tid));
        } else {
            st0[tid] = 0.f;
            st1[tid] = 0.f;
        }
    }

    wmma::fragment<wmma::accumulator, 16, 16, 16, float> acc[8];
#pragma unroll
    for (int nt = 0; nt < 8; nt++) wmma::fill_fragment(acc[nt], 0.f);

    const float4* A4 = (const float4*)A;
    const float4* W4 = (const float4*)W;

    for (int hh = 0; hh < 2; hh++) {
        int kb = hh * 64;
        __syncthreads();
        // ---- stage A half [128 x 64] as fp16 ----
#pragma unroll
        for (int it = 0; it < 8; it++) {
            int idx = it * 256 + tid;
            int row = idx >> 4;
            int c4  = idx & 15;
            int grow = row_base + row;
            float4 a = make_float4(0.f, 0.f, 0.f, 0.f);
            if (grow < M) {
                a = __ldg(A4 + (size_t)grow * 32 + (kb >> 2) + c4);
                if (MODE == 1) {
                    int gc = kb + c4 * 4;
                    a.x = fmaxf(fmaf(a.x, sc_s[gc + 0], sh_s[gc + 0]), 0.f);
                    a.y = fmaxf(fmaf(a.y, sc_s[gc + 1], sh_s[gc + 1]), 0.f);
                    a.z = fmaxf(fmaf(a.z, sc_s[gc + 2], sh_s[gc + 2]), 0.f);
                    a.w = fmaxf(fmaf(a.w, sc_s[gc + 3], sh_s[gc + 3]), 0.f);
                }
            }
            __half2 p0 = __floats2half2_rn(a.x, a.y);
            __half2 p1 = __floats2half2_rn(a.z, a.w);
            int off = row * LDA + c4 * 4;
            *(uint2*)(Ah + off) = make_uint2(*(u32*)&p0, *(u32*)&p1);
        }
        // ---- stage B = W half [64 x 128] as fp16 hi/lo ----
#pragma unroll
        for (int it = 0; it < 8; it++) {
            int idx = it * 256 + tid;
            int k  = idx >> 5;
            int n4 = idx & 31;
            float4 w = __ldg(W4 + (size_t)(kb + k) * 32 + n4);
            float v[4] = {w.x, w.y, w.z, w.w};
            unsigned short h[4], l[4];
#pragma unroll
            for (int e = 0; e < 4; e++) {
                __half hb = __float2half_rn(v[e]);
                float hf = __half2float(hb);
                __half lb = __float2half_rn(v[e] - hf);
                h[e] = *reinterpret_cast<unsigned short*>(&hb);
                l[e] = *reinterpret_cast<unsigned short*>(&lb);
            }
            int off = k * LDB + n4 * 4;
            *(uint2*)(Bh + off) = make_uint2((u32)h[0] | ((u32)h[1] << 16),
                                             (u32)h[2] | ((u32)h[3] << 16));
            *(uint2*)(Bl + off) = make_uint2((u32)l[0] | ((u32)l[1] << 16),
                                             (u32)l[2] | ((u32)l[3] << 16));
        }
        __syncthreads();
        // ---- mma: each warp = 16 rows x 128 cols, 2-pass ----
        int wrow = wid * 16;
        wmma::fragment<wmma::matrix_a, 16, 16, 16, __half, wmma::row_major> fah;
        wmma::fragment<wmma::matrix_b, 16, 16, 16, __half, wmma::row_major> fbh, fbl;
#pragma unroll
        for (int kc = 0; kc < 4; kc++) {
            wmma::load_matrix_sync(fah, Ah + wrow * LDA + kc * 16, LDA);
#pragma unroll
            for (int nt = 0; nt < 8; nt++) {
                wmma::load_matrix_sync(fbh, Bh + (kc * 16) * LDB + nt * 16, LDB);
                wmma::load_matrix_sync(fbl, Bl + (kc * 16) * LDB + nt * 16, LDB);
                wmma::mma_sync(acc[nt], fah, fbh, acc[nt]);
                wmma::mma_sync(acc[nt], fah, fbl, acc[nt]);
            }
        }
    }
    __syncthreads();   // all tile reads done; reuse tile smem for C staging

    // ---- epilogue ----
    float* Cw = (float*)(sm + TILE_OFF) + wid * 16 * 132;
#pragma unroll
    for (int nt = 0; nt < 8; nt++)
        wmma::store_matrix_sync(Cw + nt * 16, acc[nt], 132, wmma::mem_row_major);
    __syncwarp();

    float bv[4];
#pragma unroll
    for (int e = 0; e < 4; e++) bv[e] = __ldg(bias + lane * 4 + e);
    float cs[4] = {0.f, 0.f, 0.f, 0.f}, cq[4] = {0.f, 0.f, 0.f, 0.f};
#pragma unroll
    for (int i = 0; i < 16; i++) {
        int row = row_base + wid * 16 + i;
        if (row < M) {
            float4 o = *(float4*)(Cw + i * 132 + lane * 4);
            o.x += bv[0]; o.y += bv[1]; o.z += bv[2]; o.w += bv[3];
            if (MODE == 1) {
                o.x = fmaxf(o.x, 0.f); o.y = fmaxf(o.y, 0.f);
                o.z = fmaxf(o.z, 0.f); o.w = fmaxf(o.w, 0.f);
            }
            *(float4*)(out + (size_t)row * D + lane * 4) = o;
            if (MODE == 0) {
                cs[0] += o.x; cq[0] += o.x * o.x;
                cs[1] += o.y; cq[1] += o.y * o.y;
                cs[2] += o.z; cq[2] += o.z * o.z;
                cs[3] += o.w; cq[3] += o.w * o.w;
            }
        }
    }
    if (MODE == 0) {
#pragma unroll
        for (int e = 0; e < 4; e++) {
            atomicAdd(&st0[lane * 4 + e], cs[e]);
            atomicAdd(&st1[lane * 4 + e], cq[e]);
        }
        __syncthreads();
        if (tid < D) {
            atomicAdd(&ssum[tid], st0[tid]);
            atomicAdd(&ssq[tid], st1[tid]);
        }
    }
}

extern "C" void kernel_launch(void* const* d_in, const int* in_sizes, int n_in,
                              void* d_out, int out_size) {
    const float* x     = (const float*)d_in[0];
    const int*   ei    = (const int*)d_in[1];
    const float* ea    = (const float*)d_in[2];
    const float* W1    = (const float*)d_in[3];
    const float* b1    = (const float*)d_in[4];
    const float* gamma = (const float*)d_in[5];
    const float* beta  = (const float*)d_in[6];
    const float* W2    = (const float*)d_in[7];
    const float* b2    = (const float*)d_in[8];

    int M = in_sizes[0] / D;
    int E = in_sizes[2] / D;
    int L = in_sizes[3] / (D * D);
    float invN = 1.0f / (float)M;

    float *p_agg, *p_h, *p_x1, *p_sum, *p_sq;
    int *p_cnt, *p_rowptr, *p_fill, *p_perm, *p_se, *p_bsum, *p_ready;
    cudaGetSymbolAddress((void**)&p_agg,   g_agg);
    cudaGetSymbolAddress((void**)&p_h,     g_h);
    cudaGetSymbolAddress((void**)&p_x1,    g_x1);
    cudaGetSymbolAddress((void**)&p_sum,   g_sum);
    cudaGetSymbolAddress((void**)&p_sq,    g_sq);
    cudaGetSymbolAddress((void**)&p_cnt,    g_cnt);
    cudaGetSymbolAddress((void**)&p_rowptr, g_rowptr);
    cudaGetSymbolAddress((void**)&p_fill,   g_fill);
    cudaGetSymbolAddress((void**)&p_perm,   g_perm);
    cudaGetSymbolAddress((void**)&p_se,     g_se);
    cudaGetSymbolAddress((void**)&p_bsum,   g_bsum);
    cudaGetSymbolAddress((void**)&p_ready,  g_ready);

    cudaFuncSetAttribute(tc_gemm_kernel<0>, cudaFuncAttributeMaxDynamicSharedMemorySize, TCSMEM);
    cudaFuncSetAttribute(tc_gemm_kernel<1>, cudaFuncAttributeMaxDynamicSharedMemorySize, TCSMEM);

    int gemm_blocks = (M + 127) / 128;
    int eb = (E + 255) / 256;
    int nbscan = (M + SCAN_B - 1) / SCAN_B;
    int agg_blocks = (M + 7) / 8;

    // ---- build CSR once: 3 launches (hist, scan, scatter) ----
    hist_kernel<<<eb, 256>>>(ei, p_cnt, E);
    scan_kernel<<<nbscan, SCAN_B>>>(p_cnt, p_rowptr, p_fill, p_bsum, p_ready, M);
    scatter_kernel<<<eb, 256>>>(ei, p_fill, p_perm, p_se, p_cnt, p_ready, E, M);

    for (int l = 0; l < L; l++) {
        const float* xin = (l == 0) ? x : p_x1;
        float* xout = (l == L - 1) ? (float*)d_out : p_x1;

        agg_kernel<<<agg_blocks, 256>>>(xin, ea, p_rowptr, p_fill, p_perm, p_se,
                                        p_agg, p_sum, p_sq, M);
        tc_gemm_kernel<0><<<gemm_blocks, 256, TCSMEM>>>(p_agg,
            W1 + (size_t)l * D * D, b1 + (size_t)l * D,
            nullptr, nullptr, 0.f, p_h, p_sum, p_sq, M);
        tc_gemm_kernel<1><<<gemm_blocks, 256, TCSMEM>>>(p_h,
            W2 + (size_t)l * D * D, b2 + (size_t)l * D,
            gamma + (size_t)l * D, beta + (size_t)l * D, invN,
            xout, p_sum, p_sq, M);
    }
}